// round 13
// baseline (speedup 1.0000x reference)
#include <cuda_runtime.h>
#include <cuda_bf16.h>
#include <cuda_fp16.h>
#include <cstdint>
#include <math.h>

#define BSZ 2
#define SEQ 2048
#define DIM 2048
#define NH 16
#define HD 128
#define M_TOT (BSZ * SEQ)   // 4096

typedef __nv_bfloat16 bf16;

// ---------------- scratch (device globals; no allocs allowed) ----------------
__device__ float g_q[(size_t)M_TOT * DIM];
__device__ float g_k[(size_t)M_TOT * DIM];
__device__ float g_v[(size_t)M_TOT * DIM];
__device__ __half g_x16[(size_t)M_TOT * DIM];
__device__ __half g_w16h[(size_t)4 * DIM * DIM];
__device__ __half g_w16l[(size_t)4 * DIM * DIM];   // residual * 2048
__device__ __half g_ao16[(size_t)M_TOT * DIM];
__device__ bf16 g_qh[(size_t)M_TOT * DIM], g_ql[(size_t)M_TOT * DIM];
__device__ bf16 g_kh[(size_t)M_TOT * DIM], g_kl[(size_t)M_TOT * DIM];
__device__ bf16 g_vh[(size_t)M_TOT * DIM], g_vl[(size_t)M_TOT * DIM];

#define WSCL 2048.0f
#define WSCL_INV 4.8828125e-4f

// ---------------- PTX helpers ----------------
__device__ __forceinline__ uint32_t smem_u32(const void* p) {
    uint32_t a;
    asm("{ .reg .u64 t; cvta.to.shared.u64 t, %1; cvt.u32.u64 %0, t; }" : "=r"(a) : "l"(p));
    return a;
}
__device__ __forceinline__ void ldsm_x4(uint32_t* r, uint32_t addr) {
    asm volatile("ldmatrix.sync.aligned.m8n8.x4.shared.b16 {%0,%1,%2,%3}, [%4];"
                 : "=r"(r[0]), "=r"(r[1]), "=r"(r[2]), "=r"(r[3]) : "r"(addr));
}
__device__ __forceinline__ void ldsm_x2(uint32_t* r, uint32_t addr) {
    asm volatile("ldmatrix.sync.aligned.m8n8.x2.shared.b16 {%0,%1}, [%2];"
                 : "=r"(r[0]), "=r"(r[1]) : "r"(addr));
}
__device__ __forceinline__ void ldsm_x2t(uint32_t* r, uint32_t addr) {
    asm volatile("ldmatrix.sync.aligned.m8n8.x2.trans.shared.b16 {%0,%1}, [%2];"
                 : "=r"(r[0]), "=r"(r[1]) : "r"(addr));
}
// bf16 mma (flash)
__device__ __forceinline__ void mma16816(float* d, const uint32_t* a, const uint32_t* b) {
    asm volatile(
        "mma.sync.aligned.m16n8k16.row.col.f32.bf16.bf16.f32 "
        "{%0,%1,%2,%3}, {%4,%5,%6,%7}, {%8,%9}, {%0,%1,%2,%3};"
        : "+f"(d[0]), "+f"(d[1]), "+f"(d[2]), "+f"(d[3])
        : "r"(a[0]), "r"(a[1]), "r"(a[2]), "r"(a[3]), "r"(b[0]), "r"(b[1]));
}
// fp16 mma (projections)
__device__ __forceinline__ void mma16816h(float* d, const uint32_t* a, const uint32_t* b) {
    asm volatile(
        "mma.sync.aligned.m16n8k16.row.col.f32.f16.f16.f32 "
        "{%0,%1,%2,%3}, {%4,%5,%6,%7}, {%8,%9}, {%0,%1,%2,%3};"
        : "+f"(d[0]), "+f"(d[1]), "+f"(d[2]), "+f"(d[3])
        : "r"(a[0]), "r"(a[1]), "r"(a[2]), "r"(a[3]), "r"(b[0]), "r"(b[1]));
}
__device__ __forceinline__ void cp16(uint32_t dst, const void* src) {
    asm volatile("cp.async.cg.shared.global [%0], [%1], 16;" :: "r"(dst), "l"(src) : "memory");
}
#define CP_COMMIT() asm volatile("cp.async.commit_group;" ::: "memory")
#define CP_WAIT(n)  asm volatile("cp.async.wait_group %0;" :: "n"(n) : "memory")

// FFMA-only exp2 (x <= 0 path)
__device__ __forceinline__ float exp2_fast(float x) {
    x = fmaxf(x, -125.f);
    float r = x + 12582912.f;
    int  e = __float_as_int(r) - 0x4B400000;
    float f = x - (r - 12582912.f);
    float p = 1.5403530e-4f;
    p = fmaf(p, f, 1.3333558e-3f);
    p = fmaf(p, f, 9.6181291e-3f);
    p = fmaf(p, f, 5.5504109e-2f);
    p = fmaf(p, f, 2.4022651e-1f);
    p = fmaf(p, f, 6.9314718e-1f);
    p = fmaf(p, f, 1.0f);
    return __int_as_float(__float_as_int(p) + (e << 23));
}

// split floats -> packed bf16 hi + bf16 residual lo (flash path)
__device__ __forceinline__ void split2(float a, float b, uint32_t& hi, uint32_t& lo) {
    bf16 ha = __float2bfloat16_rn(a), hb = __float2bfloat16_rn(b);
    float ra = a - __bfloat162float(ha), rb = b - __bfloat162float(hb);
    __nv_bfloat162 hp = __halves2bfloat162(ha, hb);
    __nv_bfloat162 lp = __floats2bfloat162_rn(ra, rb);
    hi = *(uint32_t*)&hp;
    lo = *(uint32_t*)&lp;
}

// ---------------- prep kernels ----------------
__global__ void cvt_x16(const float* __restrict__ src, __half* __restrict__ dst, int n2) {
    int i = blockIdx.x * blockDim.x + threadIdx.x;
    if (i >= n2) return;
    float2 v = *(const float2*)(src + 2 * (size_t)i);
    __half2 h = __floats2half2_rn(v.x, v.y);
    *(uint32_t*)(dst + 2 * (size_t)i) = *(uint32_t*)&h;
}
__global__ void split_w16(const float* __restrict__ src, __half* __restrict__ hi,
                          __half* __restrict__ lo, int n2) {
    int i = blockIdx.x * blockDim.x + threadIdx.x;
    if (i >= n2) return;
    float2 v = *(const float2*)(src + 2 * (size_t)i);
    __half h0 = __float2half_rn(v.x), h1 = __float2half_rn(v.y);
    float r0 = (v.x - __half2float(h0)) * WSCL;
    float r1 = (v.y - __half2float(h1)) * WSCL;
    __half2 hp = __halves2half2(h0, h1);
    __half2 lp = __floats2half2_rn(r0, r1);
    *(uint32_t*)(hi + 2 * (size_t)i) = *(uint32_t*)&hp;
    *(uint32_t*)(lo + 2 * (size_t)i) = *(uint32_t*)&lp;
}

// ---------------- rope + convert q,k,v to bf16 hi/lo for flash ----------------
#define SQ 0.127526015f   // log2(e) / sqrt(128)
__global__ void rope_cvt(const float* __restrict__ q, const float* __restrict__ k,
                         const float* __restrict__ v,
                         const float* __restrict__ cs, const float* __restrict__ sn,
                         bf16* qh, bf16* ql, bf16* kh, bf16* kl, bf16* vh, bf16* vl) {
    int p = blockIdx.x * blockDim.x + threadIdx.x;
    const int NP = M_TOT * DIM / 2;
    if (p >= NP) return;
    int row = p / (DIM / 2), pr = p % (DIM / 2);
    int hh = pr / (HD / 2), i = pr % (HD / 2);
    int s = row % SEQ;
    float c  = cs[s * (HD / 2) + i];
    float sn_ = sn[s * (HD / 2) + i];
    size_t off = (size_t)row * DIM + hh * HD + 2 * i;
    float2 qv = *(const float2*)(q + off);
    float2 kv = *(const float2*)(k + off);
    float2 vv = *(const float2*)(v + off);
    float q0 = (qv.x * c - qv.y * sn_) * SQ, q1 = (qv.x * sn_ + qv.y * c) * SQ;
    float k0 = kv.x * c - kv.y * sn_,        k1 = kv.x * sn_ + kv.y * c;
    uint32_t h, l;
    split2(q0, q1, h, l);     *(uint32_t*)(qh + off) = h; *(uint32_t*)(ql + off) = l;
    split2(k0, k1, h, l);     *(uint32_t*)(kh + off) = h; *(uint32_t*)(kl + off) = l;
    split2(vv.x, vv.y, h, l); *(uint32_t*)(vh + off) = h; *(uint32_t*)(vl + off) = l;
}

// ===========================================================================
// fp16 GEMM, 2-pass B-split: C = Ah@Bh^T + (Ah@Bls^T)/2048.
// 128x128 tile, 8 warps 2x4, KC=64, 3-stage cp.async, one sync per chunk.
// ===========================================================================
#define KC 64
#define ASTR 72
#define GTILE (128 * ASTR)
#define STAGE_ELEMS (3 * GTILE)
#define GEMM_SMEM (3 * STAGE_ELEMS * 2)   // 165888 bytes

__global__ __launch_bounds__(256) void gemm_f16(
    const __half* __restrict__ A,
    const __half* __restrict__ Bh_all, const __half* __restrict__ Bl_all,
    float* __restrict__ C0, float* __restrict__ C1, float* __restrict__ C2) {
    extern __shared__ __half sm[];
    int z = blockIdx.z;
    const __half* Bh = Bh_all + (size_t)z * DIM * DIM;
    const __half* Bl = Bl_all + (size_t)z * DIM * DIM;
    float* C = (z == 0) ? C0 : (z == 1) ? C1 : C2;

    int t = threadIdx.x, lane = t & 31, warp = t >> 5;
    int wm = (warp & 1) * 64, wn = (warp >> 1) * 32;
    int bm = blockIdx.y * 128, bn = blockIdx.x * 128;
    const __half* Ag  = A  + (size_t)bm * DIM;
    const __half* Bgh = Bh + (size_t)bn * DIM;
    const __half* Bgl = Bl + (size_t)bn * DIM;
    uint32_t sb = smem_u32(sm);

    float acc1[4][4][4], acc2[4][4][4];
#pragma unroll
    for (int i = 0; i < 4; i++)
#pragma unroll
        for (int j = 0; j < 4; j++)
#pragma unroll
            for (int r = 0; r < 4; r++) { acc1[i][j][r] = 0.f; acc2[i][j][r] = 0.f; }

    const int NCH = DIM / KC;   // 32

#define STAGE_LOAD(S, CC)                                                        \
    {                                                                            \
        int k0_ = (CC) * KC;                                                     \
        uint32_t ds = sb + (uint32_t)((S) * STAGE_ELEMS) * 2;                    \
        _Pragma("unroll")                                                        \
        for (int i_ = 0; i_ < 4; i_++) {                                         \
            int li = t + 256 * i_;                                               \
            int rr = li >> 3, seg = li & 7;                                      \
            uint32_t so = (uint32_t)(rr * ASTR + seg * 8) * 2;                   \
            size_t go = (size_t)rr * DIM + k0_ + seg * 8;                        \
            cp16(ds + so,                 Ag + go);                              \
            cp16(ds + GTILE * 2 + so,     Bgh + go);                             \
            cp16(ds + 2 * GTILE * 2 + so, Bgl + go);                             \
        }                                                                        \
    }

    STAGE_LOAD(0, 0);
    CP_COMMIT();
    STAGE_LOAD(1, 1);
    CP_COMMIT();

    for (int c = 0; c < NCH; c++) {
        if (c + 2 < NCH) CP_WAIT(1); else CP_WAIT(0);
        __syncthreads();
        if (c + 2 < NCH) {
            STAGE_LOAD((c + 2) % 3, c + 2);
            CP_COMMIT();
        }

        int s = c % 3;
        uint32_t Ab  = sb + (uint32_t)(s * STAGE_ELEMS) * 2;
        uint32_t Bb  = Ab + GTILE * 2;
        uint32_t Blb = Ab + 2 * GTILE * 2;

#pragma unroll
        for (int ks = 0; ks < 4; ks++) {
            uint32_t ah[4][4], bh[4][2], bl[4][2];
#pragma unroll
            for (int i = 0; i < 4; i++) {
                uint32_t ao = (uint32_t)((wm + i * 16 + (lane & 15)) * ASTR + ks * 16 + (lane >> 4) * 8) * 2;
                ldsm_x4(ah[i], Ab + ao);
            }
#pragma unroll
            for (int j = 0; j < 4; j++) {
                uint32_t bo = (uint32_t)((wn + j * 8 + (lane & 7)) * ASTR + ks * 16 + ((lane >> 3) & 1) * 8) * 2;
                ldsm_x2(bh[j], Bb + bo);
                ldsm_x2(bl[j], Blb + bo);
            }
#pragma unroll
            for (int i = 0; i < 4; i++)
#pragma unroll
                for (int j = 0; j < 4; j++) mma16816h(acc1[i][j], ah[i], bh[j]);
#pragma unroll
            for (int i = 0; i < 4; i++)
#pragma unroll
                for (int j = 0; j < 4; j++) mma16816h(acc2[i][j], ah[i], bl[j]);
        }
    }

#pragma unroll
    for (int i = 0; i < 4; i++) {
        int r0 = bm + wm + i * 16 + (lane >> 2);
#pragma unroll
        for (int j = 0; j < 4; j++) {
            int c0 = bn + wn + j * 8 + (lane & 3) * 2;
            float v0 = fmaf(acc2[i][j][0], WSCL_INV, acc1[i][j][0]);
            float v1 = fmaf(acc2[i][j][1], WSCL_INV, acc1[i][j][1]);
            float v2 = fmaf(acc2[i][j][2], WSCL_INV, acc1[i][j][2]);
            float v3 = fmaf(acc2[i][j][3], WSCL_INV, acc1[i][j][3]);
            *(float2*)(C + (size_t)r0 * DIM + c0)       = make_float2(v0, v1);
            *(float2*)(C + (size_t)(r0 + 8) * DIM + c0) = make_float2(v2, v3);
        }
    }
}

// ===========================================================================
// Flash attention, mma.sync bf16 3-pass split, causal. BR=128, BC=64,
// double-buffered K/V, one sync per k-tile. Output: fp16 (for out-proj A side).
// ===========================================================================
#define FSTR 136
#define QT (128 * FSTR)
#define KT (64 * FSTR)
#define FSTAGE (4 * KT)
#define FLASH_SMEM ((2 * QT + 2 * FSTAGE) * 2)   // 208896 bytes

__global__ __launch_bounds__(256) void flash_mma(
    const bf16* __restrict__ qh, const bf16* __restrict__ ql,
    const bf16* __restrict__ kh, const bf16* __restrict__ kl,
    const bf16* __restrict__ vh, const bf16* __restrict__ vl,
    __half* __restrict__ ao16) {
    extern __shared__ bf16 fsm[];
    int t = threadIdx.x, lane = t & 31, warp = t >> 5;
    int qblk = gridDim.x - 1 - blockIdx.x;
    int hh = blockIdx.y, b = blockIdx.z;
    int q0 = qblk * 128;
    size_t hb = (size_t)b * SEQ * DIM + (size_t)hh * HD;
    uint32_t sb = smem_u32(fsm);
    uint32_t Qh_s = sb, Ql_s = sb + QT * 2;
    uint32_t KV0  = sb + 2 * QT * 2;

#define FKV_LOAD(S, KT0)                                                         \
    {                                                                            \
        uint32_t ds = KV0 + (uint32_t)((S) * FSTAGE) * 2;                        \
        _Pragma("unroll")                                                        \
        for (int i_ = 0; i_ < 4; i_++) {                                         \
            int li = t + 256 * i_;                                               \
            int rr = li >> 4, seg = li & 15;                                     \
            size_t g = hb + (size_t)((KT0) + rr) * DIM + seg * 8;                \
            uint32_t so = (uint32_t)(rr * FSTR + seg * 8) * 2;                   \
            cp16(ds + so,              kh + g);                                  \
            cp16(ds + KT * 2 + so,     kl + g);                                  \
            cp16(ds + 2 * KT * 2 + so, vh + g);                                  \
            cp16(ds + 3 * KT * 2 + so, vl + g);                                  \
        }                                                                        \
    }

#pragma unroll
    for (int i = 0; i < 8; i++) {
        int li = t + 256 * i;
        int r = li >> 4, seg = li & 15;
        size_t g = hb + (size_t)(q0 + r) * DIM + seg * 8;
        uint32_t so = (uint32_t)(r * FSTR + seg * 8) * 2;
        cp16(Qh_s + so, qh + g);
        cp16(Ql_s + so, ql + g);
    }
    FKV_LOAD(0, 0);
    CP_COMMIT();

    float accO[16][4];
#pragma unroll
    for (int j = 0; j < 16; j++)
#pragma unroll
        for (int r = 0; r < 4; r++) accO[j][r] = 0.f;
    float m0 = -1e30f, m1 = -1e30f, l0 = 0.f, l1 = 0.f;
    int rl0 = 16 * warp + (lane >> 2), rl1 = rl0 + 8;
    int r0g = q0 + rl0, r1g = q0 + rl1;

    int nk = 2 * qblk + 2;
    for (int kt = 0; kt < nk; kt++) {
        int k0 = kt * 64;
        CP_WAIT(0);
        __syncthreads();
        if (kt + 1 < nk) {
            FKV_LOAD((kt + 1) & 1, k0 + 64);
            CP_COMMIT();
        }
        uint32_t Kh_s = KV0 + (uint32_t)((kt & 1) * FSTAGE) * 2;
        uint32_t Kl_s = Kh_s + KT * 2;
        uint32_t Vh_s = Kh_s + 2 * KT * 2;
        uint32_t Vl_s = Kh_s + 3 * KT * 2;

        float accS[8][4];
#pragma unroll
        for (int j = 0; j < 8; j++)
#pragma unroll
            for (int r = 0; r < 4; r++) accS[j][r] = 0.f;

#pragma unroll
        for (int ks = 0; ks < 8; ks++) {
            uint32_t qf_h[4], qf_l[4];
            uint32_t ao = (uint32_t)((16 * warp + (lane & 15)) * FSTR + ks * 16 + (lane >> 4) * 8) * 2;
            ldsm_x4(qf_h, Qh_s + ao);
            ldsm_x4(qf_l, Ql_s + ao);
#pragma unroll
            for (int j = 0; j < 8; j++) {
                uint32_t bo = (uint32_t)((8 * j + (lane & 7)) * FSTR + ks * 16 + ((lane >> 3) & 1) * 8) * 2;
                uint32_t kf[2], kf2[2];
                ldsm_x2(kf, Kh_s + bo);
                mma16816(accS[j], qf_h, kf);
                mma16816(accS[j], qf_l, kf);
                ldsm_x2(kf2, Kl_s + bo);
                mma16816(accS[j], qf_h, kf2);
            }
        }

        if (kt >= 2 * qblk) {
            int cb = 2 * (lane & 3);
#pragma unroll
            for (int j = 0; j < 8; j++) {
                int c0 = k0 + 8 * j + cb;
                if (c0 > r0g)     accS[j][0] = -1e30f;
                if (c0 + 1 > r0g) accS[j][1] = -1e30f;
                if (c0 > r1g)     accS[j][2] = -1e30f;
                if (c0 + 1 > r1g) accS[j][3] = -1e30f;
            }
        }

        float mx0 = -1e30f, mx1 = -1e30f;
#pragma unroll
        for (int j = 0; j < 8; j++) {
            mx0 = fmaxf(mx0, fmaxf(accS[j][0], accS[j][1]));
            mx1 = fmaxf(mx1, fmaxf(accS[j][2], accS[j][3]));
        }
        mx0 = fmaxf(mx0, __shfl_xor_sync(0xffffffffu, mx0, 1));
        mx0 = fmaxf(mx0, __shfl_xor_sync(0xffffffffu, mx0, 2));
        mx1 = fmaxf(mx1, __shfl_xor_sync(0xffffffffu, mx1, 1));
        mx1 = fmaxf(mx1, __shfl_xor_sync(0xffffffffu, mx1, 2));
        float mn0 = fmaxf(m0, mx0), mn1 = fmaxf(m1, mx1);
        float cr0 = exp2_fast(m0 - mn0), cr1 = exp2_fast(m1 - mn1);
        float s0 = 0.f, s1 = 0.f;
#pragma unroll
        for (int j = 0; j < 8; j++) {
            accS[j][0] = exp2_fast(accS[j][0] - mn0); s0 += accS[j][0];
            accS[j][1] = exp2_fast(accS[j][1] - mn0); s0 += accS[j][1];
            accS[j][2] = exp2_fast(accS[j][2] - mn1); s1 += accS[j][2];
            accS[j][3] = exp2_fast(accS[j][3] - mn1); s1 += accS[j][3];
        }
        s0 += __shfl_xor_sync(0xffffffffu, s0, 1);
        s0 += __shfl_xor_sync(0xffffffffu, s0, 2);
        s1 += __shfl_xor_sync(0xffffffffu, s1, 1);
        s1 += __shfl_xor_sync(0xffffffffu, s1, 2);
        l0 = l0 * cr0 + s0;
        l1 = l1 * cr1 + s1;
        m0 = mn0; m1 = mn1;
#pragma unroll
        for (int j = 0; j < 16; j++) {
            accO[j][0] *= cr0; accO[j][1] *= cr0;
            accO[j][2] *= cr1; accO[j][3] *= cr1;
        }

#pragma unroll
        for (int ks = 0; ks < 4; ks++) {
            int ja = 2 * ks, jb = 2 * ks + 1;
            uint32_t ph[4], pl[4];
            split2(accS[ja][0], accS[ja][1], ph[0], pl[0]);
            split2(accS[ja][2], accS[ja][3], ph[1], pl[1]);
            split2(accS[jb][0], accS[jb][1], ph[2], pl[2]);
            split2(accS[jb][2], accS[jb][3], ph[3], pl[3]);
#pragma unroll
            for (int j2 = 0; j2 < 16; j2++) {
                uint32_t vo = (uint32_t)((16 * ks + (lane & 15)) * FSTR + 8 * j2) * 2;
                uint32_t vf[2], vf2[2];
                ldsm_x2t(vf, Vh_s + vo);
                mma16816(accO[j2], ph, vf);
                mma16816(accO[j2], pl, vf);
                ldsm_x2t(vf2, Vl_s + vo);
                mma16816(accO[j2], ph, vf2);
            }
        }
    }

    // epilogue: normalize, fp16 store (out-proj drops the A-residual anyway)
    float i0 = 1.f / l0, i1 = 1.f / l1;
#pragma unroll
    for (int j2 = 0; j2 < 16; j2++) {
        int col = 8 * j2 + 2 * (lane & 3);
        size_t o0 = hb + (size_t)r0g * DIM + col;
        size_t o1 = hb + (size_t)r1g * DIM + col;
        __half2 h0 = __floats2half2_rn(accO[j2][0] * i0, accO[j2][1] * i0);
        __half2 h1 = __floats2half2_rn(accO[j2][2] * i1, accO[j2][3] * i1);
        *(uint32_t*)(ao16 + o0) = *(uint32_t*)&h0;
        *(uint32_t*)(ao16 + o1) = *(uint32_t*)&h1;
    }
}

// ---------------------------------------------------------------------------
extern "C" void kernel_launch(void* const* d_in, const int* in_sizes, int n_in,
                              void* d_out, int out_size) {
    const float* x  = (const float*)d_in[0];
    const float* wq = (const float*)d_in[1];
    const float* wk = (const float*)d_in[2];
    const float* wv = (const float*)d_in[3];
    const float* wo = (const float*)d_in[4];
    const float* fc = (const float*)d_in[5];
    const float* fs = (const float*)d_in[6];
    float* out = (float*)d_out;

    float *q, *k, *v;
    __half *x16, *w16h, *w16l, *ao16;
    bf16 *qhp, *qlp, *khp, *klp, *vhp, *vlp;
    cudaGetSymbolAddress((void**)&q,    g_q);
    cudaGetSymbolAddress((void**)&k,    g_k);
    cudaGetSymbolAddress((void**)&v,    g_v);
    cudaGetSymbolAddress((void**)&x16,  g_x16);
    cudaGetSymbolAddress((void**)&w16h, g_w16h);
    cudaGetSymbolAddress((void**)&w16l, g_w16l);
    cudaGetSymbolAddress((void**)&ao16, g_ao16);
    cudaGetSymbolAddress((void**)&qhp,  g_qh);
    cudaGetSymbolAddress((void**)&qlp,  g_ql);
    cudaGetSymbolAddress((void**)&khp,  g_kh);
    cudaGetSymbolAddress((void**)&klp,  g_kl);
    cudaGetSymbolAddress((void**)&vhp,  g_vh);
    cudaGetSymbolAddress((void**)&vlp,  g_vl);

    cudaFuncSetAttribute(gemm_f16,  cudaFuncAttributeMaxDynamicSharedMemorySize, GEMM_SMEM);
    cudaFuncSetAttribute(flash_mma, cudaFuncAttributeMaxDynamicSharedMemorySize, FLASH_SMEM);

    // 1. convert x (fp16 hi only) and split weights (fp16 hi + scaled lo)
    int nx2 = M_TOT * DIM / 2;
    int nw2 = DIM * DIM / 2;
    cvt_x16 <<<(nx2 + 255) / 256, 256>>>(x, x16, nx2);
    split_w16<<<(nw2 + 255) / 256, 256>>>(wq, w16h,                         w16l,                         nw2);
    split_w16<<<(nw2 + 255) / 256, 256>>>(wk, w16h + (size_t)1 * DIM * DIM, w16l + (size_t)1 * DIM * DIM, nw2);
    split_w16<<<(nw2 + 255) / 256, 256>>>(wv, w16h + (size_t)2 * DIM * DIM, w16l + (size_t)2 * DIM * DIM, nw2);
    split_w16<<<(nw2 + 255) / 256, 256>>>(wo, w16h + (size_t)3 * DIM * DIM, w16l + (size_t)3 * DIM * DIM, nw2);

    // 2. fused QKV projections (2-pass fp16)
    dim3 ggrid(DIM / 128, M_TOT / 128, 3);
    gemm_f16<<<ggrid, 256, GEMM_SMEM>>>(x16, w16h, w16l, q, k, v);

    // 3. rope + convert to bf16 hi/lo for flash
    int np = M_TOT * DIM / 2;
    rope_cvt<<<(np + 255) / 256, 256>>>(q, k, v, fc, fs, qhp, qlp, khp, klp, vhp, vlp);

    // 4. flash attention (bf16 3-pass, double-buffered K/V)
    dim3 fgrid(SEQ / 128, NH, BSZ);
    flash_mma<<<fgrid, 256, FLASH_SMEM>>>(qhp, qlp, khp, klp, vhp, vlp, ao16);

    // 5. output projection (2-pass fp16)
    dim3 ogrid(DIM / 128, M_TOT / 128, 1);
    gemm_f16<<<ogrid, 256, GEMM_SMEM>>>(ao16, w16h + (size_t)3 * DIM * DIM,
                                        w16l + (size_t)3 * DIM * DIM, out, out, out);
}

// round 14
// speedup vs baseline: 1.1286x; 1.1286x over previous
#include <cuda_runtime.h>
#include <cuda_bf16.h>
#include <cstdint>
#include <math.h>

#define BSZ 2
#define SEQ 2048
#define DIM 2048
#define NH 16
#define HD 128
#define M_TOT (BSZ * SEQ)   // 4096

typedef __nv_bfloat16 bf16;

// ---------------- scratch (device globals; no allocs allowed) ----------------
__device__ bf16 g_xh[(size_t)M_TOT * DIM], g_xl[(size_t)M_TOT * DIM];
__device__ bf16 g_wh[(size_t)4 * DIM * DIM], g_wl[(size_t)4 * DIM * DIM];
__device__ bf16 g_qh[(size_t)M_TOT * DIM], g_ql[(size_t)M_TOT * DIM];
__device__ bf16 g_kh[(size_t)M_TOT * DIM], g_kl[(size_t)M_TOT * DIM];
__device__ bf16 g_vh[(size_t)M_TOT * DIM], g_vl[(size_t)M_TOT * DIM];
__device__ bf16 g_aoh[(size_t)M_TOT * DIM], g_aol[(size_t)M_TOT * DIM];

// ---------------- PTX helpers ----------------
__device__ __forceinline__ uint32_t smem_u32(const void* p) {
    uint32_t a;
    asm("{ .reg .u64 t; cvta.to.shared.u64 t, %1; cvt.u32.u64 %0, t; }" : "=r"(a) : "l"(p));
    return a;
}
__device__ __forceinline__ void ldsm_x4(uint32_t* r, uint32_t addr) {
    asm volatile("ldmatrix.sync.aligned.m8n8.x4.shared.b16 {%0,%1,%2,%3}, [%4];"
                 : "=r"(r[0]), "=r"(r[1]), "=r"(r[2]), "=r"(r[3]) : "r"(addr));
}
__device__ __forceinline__ void ldsm_x2(uint32_t* r, uint32_t addr) {
    asm volatile("ldmatrix.sync.aligned.m8n8.x2.shared.b16 {%0,%1}, [%2];"
                 : "=r"(r[0]), "=r"(r[1]) : "r"(addr));
}
__device__ __forceinline__ void ldsm_x2t(uint32_t* r, uint32_t addr) {
    asm volatile("ldmatrix.sync.aligned.m8n8.x2.trans.shared.b16 {%0,%1}, [%2];"
                 : "=r"(r[0]), "=r"(r[1]) : "r"(addr));
}
__device__ __forceinline__ void mma16816(float* d, const uint32_t* a, const uint32_t* b) {
    asm volatile(
        "mma.sync.aligned.m16n8k16.row.col.f32.bf16.bf16.f32 "
        "{%0,%1,%2,%3}, {%4,%5,%6,%7}, {%8,%9}, {%0,%1,%2,%3};"
        : "+f"(d[0]), "+f"(d[1]), "+f"(d[2]), "+f"(d[3])
        : "r"(a[0]), "r"(a[1]), "r"(a[2]), "r"(a[3]), "r"(b[0]), "r"(b[1]));
}
__device__ __forceinline__ void cp16(uint32_t dst, const void* src) {
    asm volatile("cp.async.cg.shared.global [%0], [%1], 16;" :: "r"(dst), "l"(src) : "memory");
}
#define CP_COMMIT() asm volatile("cp.async.commit_group;" ::: "memory")
#define CP_WAIT(n)  asm volatile("cp.async.wait_group %0;" :: "n"(n) : "memory")

// FFMA-only exp2 (x <= 0 path)
__device__ __forceinline__ float exp2_fast(float x) {
    x = fmaxf(x, -125.f);
    float r = x + 12582912.f;
    int  e = __float_as_int(r) - 0x4B400000;
    float f = x - (r - 12582912.f);
    float p = 1.5403530e-4f;
    p = fmaf(p, f, 1.3333558e-3f);
    p = fmaf(p, f, 9.6181291e-3f);
    p = fmaf(p, f, 5.5504109e-2f);
    p = fmaf(p, f, 2.4022651e-1f);
    p = fmaf(p, f, 6.9314718e-1f);
    p = fmaf(p, f, 1.0f);
    return __int_as_float(__float_as_int(p) + (e << 23));
}

// split floats -> packed bf16 hi + bf16 residual lo
__device__ __forceinline__ void split2(float a, float b, uint32_t& hi, uint32_t& lo) {
    bf16 ha = __float2bfloat16_rn(a), hb = __float2bfloat16_rn(b);
    float ra = a - __bfloat162float(ha), rb = b - __bfloat162float(hb);
    __nv_bfloat162 hp = __halves2bfloat162(ha, hb);
    __nv_bfloat162 lp = __floats2bfloat162_rn(ra, rb);
    hi = *(uint32_t*)&hp;
    lo = *(uint32_t*)&lp;
}

// ---------------- prep: fp32 -> bf16 hi/lo ----------------
__global__ void split_kernel(const float* __restrict__ src, bf16* __restrict__ hi,
                             bf16* __restrict__ lo, int n2) {
    int i = blockIdx.x * blockDim.x + threadIdx.x;
    if (i >= n2) return;
    float2 v = *(const float2*)(src + 2 * (size_t)i);
    uint32_t h, l;
    split2(v.x, v.y, h, l);
    *(uint32_t*)(hi + 2 * (size_t)i) = h;
    *(uint32_t*)(lo + 2 * (size_t)i) = l;
}
// 4 weight matrices in one launch (grid.y selects)
__global__ void split_w4(const float* __restrict__ w0, const float* __restrict__ w1,
                         const float* __restrict__ w2, const float* __restrict__ w3,
                         bf16* __restrict__ hi, bf16* __restrict__ lo, int n2) {
    int y = blockIdx.y;
    const float* src = (y == 0) ? w0 : (y == 1) ? w1 : (y == 2) ? w2 : w3;
    bf16* h = hi + (size_t)y * DIM * DIM;
    bf16* l = lo + (size_t)y * DIM * DIM;
    int i = blockIdx.x * blockDim.x + threadIdx.x;
    if (i >= n2) return;
    float2 v = *(const float2*)(src + 2 * (size_t)i);
    uint32_t hh, ll;
    split2(v.x, v.y, hh, ll);
    *(uint32_t*)(h + 2 * (size_t)i) = hh;
    *(uint32_t*)(l + 2 * (size_t)i) = ll;
}

// ===========================================================================
// bf16 GEMM, 3-pass split, BM=128 x BN=64 tile, KC=64, 3-stage cp.async.
// MODE 0: z in {0,1,2} = q,k,v; fused RoPE (q,k) + hi/lo split epilogue.
// MODE 1: fp32 epilogue to C.
// ===========================================================================
#define KC 64
#define ASTR 72
#define ATILE (128 * ASTR)                 // 9216 elems
#define BTILE (64 * ASTR)                  // 4608 elems
#define STAGE_ELEMS (2 * ATILE + 2 * BTILE)
#define GEMM_SMEM (3 * STAGE_ELEMS * 2)    // 165888 bytes
#define SQ 0.127526015f                    // log2(e) / sqrt(128)

template <int MODE>
__global__ __launch_bounds__(256) void gemm_bf16(
    const bf16* __restrict__ Ah, const bf16* __restrict__ Al,
    const bf16* __restrict__ Bh_all, const bf16* __restrict__ Bl_all,
    float* __restrict__ C,
    bf16* __restrict__ qh, bf16* __restrict__ ql,
    bf16* __restrict__ kh, bf16* __restrict__ kl,
    bf16* __restrict__ vh, bf16* __restrict__ vl,
    const float* __restrict__ fc, const float* __restrict__ fs) {
    extern __shared__ bf16 sm[];
    int z = blockIdx.z;
    const bf16* Bh = Bh_all + (size_t)z * DIM * DIM;
    const bf16* Bl = Bl_all + (size_t)z * DIM * DIM;

    int t = threadIdx.x, lane = t & 31, warp = t >> 5;
    int wm = (warp & 1) * 64, wn = (warp >> 1) * 16;
    int bm = blockIdx.y * 128, bn = blockIdx.x * 64;
    const bf16* Agh = Ah + (size_t)bm * DIM;
    const bf16* Agl = Al + (size_t)bm * DIM;
    const bf16* Bgh = Bh + (size_t)bn * DIM;
    const bf16* Bgl = Bl + (size_t)bn * DIM;
    uint32_t sb = smem_u32(sm);

    float acc[4][2][4];
#pragma unroll
    for (int i = 0; i < 4; i++)
#pragma unroll
        for (int j = 0; j < 2; j++)
#pragma unroll
            for (int r = 0; r < 4; r++) acc[i][j][r] = 0.f;

    const int NCH = DIM / KC;   // 32

#define STAGE_LOAD(S, CC)                                                        \
    {                                                                            \
        int k0_ = (CC) * KC;                                                     \
        uint32_t ds = sb + (uint32_t)((S) * STAGE_ELEMS) * 2;                    \
        _Pragma("unroll")                                                        \
        for (int i_ = 0; i_ < 4; i_++) {                                         \
            int li = t + 256 * i_;                                               \
            int rr = li >> 3, seg = li & 7;                                      \
            uint32_t so = (uint32_t)(rr * ASTR + seg * 8) * 2;                   \
            size_t go = (size_t)rr * DIM + k0_ + seg * 8;                        \
            cp16(ds + so,             Agh + go);                                 \
            cp16(ds + ATILE * 2 + so, Agl + go);                                 \
        }                                                                        \
        _Pragma("unroll")                                                        \
        for (int i_ = 0; i_ < 2; i_++) {                                         \
            int li = t + 256 * i_;                                               \
            int rr = li >> 3, seg = li & 7;                                      \
            uint32_t so = (uint32_t)(rr * ASTR + seg * 8) * 2;                   \
            size_t go = (size_t)rr * DIM + k0_ + seg * 8;                        \
            cp16(ds + 2 * ATILE * 2 + so,             Bgh + go);                 \
            cp16(ds + (2 * ATILE + BTILE) * 2 + so,   Bgl + go);                 \
        }                                                                        \
    }

    STAGE_LOAD(0, 0);
    CP_COMMIT();
    STAGE_LOAD(1, 1);
    CP_COMMIT();

    for (int c = 0; c < NCH; c++) {
        if (c + 2 < NCH) CP_WAIT(1); else CP_WAIT(0);
        __syncthreads();
        if (c + 2 < NCH) {
            STAGE_LOAD((c + 2) % 3, c + 2);
            CP_COMMIT();
        }

        int s = c % 3;
        uint32_t Ab  = sb + (uint32_t)(s * STAGE_ELEMS) * 2;
        uint32_t Alb = Ab + ATILE * 2;
        uint32_t Bb  = Ab + 2 * ATILE * 2;
        uint32_t Blb = Ab + (2 * ATILE + BTILE) * 2;

#pragma unroll
        for (int ks = 0; ks < 4; ks++) {
            uint32_t ah[4][4], al[4][4], bh[2][2], bl[2][2];
#pragma unroll
            for (int i = 0; i < 4; i++) {
                uint32_t ao = (uint32_t)((wm + i * 16 + (lane & 15)) * ASTR + ks * 16 + (lane >> 4) * 8) * 2;
                ldsm_x4(ah[i], Ab + ao);
                ldsm_x4(al[i], Alb + ao);
            }
#pragma unroll
            for (int j = 0; j < 2; j++) {
                uint32_t bo = (uint32_t)((wn + j * 8 + (lane & 7)) * ASTR + ks * 16 + ((lane >> 3) & 1) * 8) * 2;
                ldsm_x2(bh[j], Bb + bo);
                ldsm_x2(bl[j], Blb + bo);
            }
#pragma unroll
            for (int i = 0; i < 4; i++)
#pragma unroll
                for (int j = 0; j < 2; j++) mma16816(acc[i][j], ah[i], bh[j]);
#pragma unroll
            for (int i = 0; i < 4; i++)
#pragma unroll
                for (int j = 0; j < 2; j++) mma16816(acc[i][j], ah[i], bl[j]);
#pragma unroll
            for (int i = 0; i < 4; i++)
#pragma unroll
                for (int j = 0; j < 2; j++) mma16816(acc[i][j], al[i], bh[j]);
        }
    }

    if (MODE == 1) {
#pragma unroll
        for (int i = 0; i < 4; i++) {
            int r0 = bm + wm + i * 16 + (lane >> 2);
#pragma unroll
            for (int j = 0; j < 2; j++) {
                int c0 = bn + wn + j * 8 + (lane & 3) * 2;
                *(float2*)(C + (size_t)r0 * DIM + c0)       = make_float2(acc[i][j][0], acc[i][j][1]);
                *(float2*)(C + (size_t)(r0 + 8) * DIM + c0) = make_float2(acc[i][j][2], acc[i][j][3]);
            }
        }
    } else {
        // fused RoPE (z<2) + bf16 hi/lo split epilogue
        bf16* oh = (z == 0) ? qh : (z == 1) ? kh : vh;
        bf16* ol = (z == 0) ? ql : (z == 1) ? kl : vl;
#pragma unroll
        for (int i = 0; i < 4; i++) {
            int r0 = bm + wm + i * 16 + (lane >> 2);
            int r1 = r0 + 8;
#pragma unroll
            for (int j = 0; j < 2; j++) {
                int c0 = bn + wn + j * 8 + (lane & 3) * 2;
                float a0 = acc[i][j][0], b0 = acc[i][j][1];   // row r0, cols c0, c0+1
                float a1 = acc[i][j][2], b1 = acc[i][j][3];   // row r1
                if (z < 2) {
                    int ir = (c0 & (HD - 1)) >> 1;
                    int s0r = r0 & (SEQ - 1), s1r = r1 & (SEQ - 1);
                    float c_ = fc[s0r * (HD / 2) + ir], s_ = fs[s0r * (HD / 2) + ir];
                    float t0 = a0 * c_ - b0 * s_, t1 = a0 * s_ + b0 * c_;
                    c_ = fc[s1r * (HD / 2) + ir]; s_ = fs[s1r * (HD / 2) + ir];
                    float u0 = a1 * c_ - b1 * s_, u1 = a1 * s_ + b1 * c_;
                    if (z == 0) { t0 *= SQ; t1 *= SQ; u0 *= SQ; u1 *= SQ; }
                    a0 = t0; b0 = t1; a1 = u0; b1 = u1;
                }
                uint32_t h, l;
                split2(a0, b0, h, l);
                *(uint32_t*)(oh + (size_t)r0 * DIM + c0) = h;
                *(uint32_t*)(ol + (size_t)r0 * DIM + c0) = l;
                split2(a1, b1, h, l);
                *(uint32_t*)(oh + (size_t)r1 * DIM + c0) = h;
                *(uint32_t*)(ol + (size_t)r1 * DIM + c0) = l;
            }
        }
    }
}

// ===========================================================================
// Flash attention, mma.sync bf16 3-pass split, causal. BR=128, BC=64,
// double-buffered K/V, one sync per k-tile. Outputs bf16 hi/lo. (R10-proven)
// ===========================================================================
#define FSTR 136
#define QT (128 * FSTR)
#define KT (64 * FSTR)
#define FSTAGE (4 * KT)
#define FLASH_SMEM ((2 * QT + 2 * FSTAGE) * 2)   // 208896 bytes

__global__ __launch_bounds__(256) void flash_mma(
    const bf16* __restrict__ qh, const bf16* __restrict__ ql,
    const bf16* __restrict__ kh, const bf16* __restrict__ kl,
    const bf16* __restrict__ vh, const bf16* __restrict__ vl,
    bf16* __restrict__ aoh, bf16* __restrict__ aol) {
    extern __shared__ bf16 fsm[];
    int t = threadIdx.x, lane = t & 31, warp = t >> 5;
    int qblk = gridDim.x - 1 - blockIdx.x;
    int hh = blockIdx.y, b = blockIdx.z;
    int q0 = qblk * 128;
    size_t hb = (size_t)b * SEQ * DIM + (size_t)hh * HD;
    uint32_t sb = smem_u32(fsm);
    uint32_t Qh_s = sb, Ql_s = sb + QT * 2;
    uint32_t KV0  = sb + 2 * QT * 2;

#define FKV_LOAD(S, KT0)                                                         \
    {                                                                            \
        uint32_t ds = KV0 + (uint32_t)((S) * FSTAGE) * 2;                        \
        _Pragma("unroll")                                                        \
        for (int i_ = 0; i_ < 4; i_++) {                                         \
            int li = t + 256 * i_;                                               \
            int rr = li >> 4, seg = li & 15;                                     \
            size_t g = hb + (size_t)((KT0) + rr) * DIM + seg * 8;                \
            uint32_t so = (uint32_t)(rr * FSTR + seg * 8) * 2;                   \
            cp16(ds + so,              kh + g);                                  \
            cp16(ds + KT * 2 + so,     kl + g);                                  \
            cp16(ds + 2 * KT * 2 + so, vh + g);                                  \
            cp16(ds + 3 * KT * 2 + so, vl + g);                                  \
        }                                                                        \
    }

#pragma unroll
    for (int i = 0; i < 8; i++) {
        int li = t + 256 * i;
        int r = li >> 4, seg = li & 15;
        size_t g = hb + (size_t)(q0 + r) * DIM + seg * 8;
        uint32_t so = (uint32_t)(r * FSTR + seg * 8) * 2;
        cp16(Qh_s + so, qh + g);
        cp16(Ql_s + so, ql + g);
    }
    FKV_LOAD(0, 0);
    CP_COMMIT();

    float accO[16][4];
#pragma unroll
    for (int j = 0; j < 16; j++)
#pragma unroll
        for (int r = 0; r < 4; r++) accO[j][r] = 0.f;
    float m0 = -1e30f, m1 = -1e30f, l0 = 0.f, l1 = 0.f;
    int rl0 = 16 * warp + (lane >> 2), rl1 = rl0 + 8;
    int r0g = q0 + rl0, r1g = q0 + rl1;

    int nk = 2 * qblk + 2;
    for (int kt = 0; kt < nk; kt++) {
        int k0 = kt * 64;
        CP_WAIT(0);
        __syncthreads();
        if (kt + 1 < nk) {
            FKV_LOAD((kt + 1) & 1, k0 + 64);
            CP_COMMIT();
        }
        uint32_t Kh_s = KV0 + (uint32_t)((kt & 1) * FSTAGE) * 2;
        uint32_t Kl_s = Kh_s + KT * 2;
        uint32_t Vh_s = Kh_s + 2 * KT * 2;
        uint32_t Vl_s = Kh_s + 3 * KT * 2;

        float accS[8][4];
#pragma unroll
        for (int j = 0; j < 8; j++)
#pragma unroll
            for (int r = 0; r < 4; r++) accS[j][r] = 0.f;

#pragma unroll
        for (int ks = 0; ks < 8; ks++) {
            uint32_t qf_h[4], qf_l[4];
            uint32_t ao = (uint32_t)((16 * warp + (lane & 15)) * FSTR + ks * 16 + (lane >> 4) * 8) * 2;
            ldsm_x4(qf_h, Qh_s + ao);
            ldsm_x4(qf_l, Ql_s + ao);
#pragma unroll
            for (int j = 0; j < 8; j++) {
                uint32_t bo = (uint32_t)((8 * j + (lane & 7)) * FSTR + ks * 16 + ((lane >> 3) & 1) * 8) * 2;
                uint32_t kf[2], kf2[2];
                ldsm_x2(kf, Kh_s + bo);
                mma16816(accS[j], qf_h, kf);
                mma16816(accS[j], qf_l, kf);
                ldsm_x2(kf2, Kl_s + bo);
                mma16816(accS[j], qf_h, kf2);
            }
        }

        if (kt >= 2 * qblk) {
            int cb = 2 * (lane & 3);
#pragma unroll
            for (int j = 0; j < 8; j++) {
                int c0 = k0 + 8 * j + cb;
                if (c0 > r0g)     accS[j][0] = -1e30f;
                if (c0 + 1 > r0g) accS[j][1] = -1e30f;
                if (c0 > r1g)     accS[j][2] = -1e30f;
                if (c0 + 1 > r1g) accS[j][3] = -1e30f;
            }
        }

        float mx0 = -1e30f, mx1 = -1e30f;
#pragma unroll
        for (int j = 0; j < 8; j++) {
            mx0 = fmaxf(mx0, fmaxf(accS[j][0], accS[j][1]));
            mx1 = fmaxf(mx1, fmaxf(accS[j][2], accS[j][3]));
        }
        mx0 = fmaxf(mx0, __shfl_xor_sync(0xffffffffu, mx0, 1));
        mx0 = fmaxf(mx0, __shfl_xor_sync(0xffffffffu, mx0, 2));
        mx1 = fmaxf(mx1, __shfl_xor_sync(0xffffffffu, mx1, 1));
        mx1 = fmaxf(mx1, __shfl_xor_sync(0xffffffffu, mx1, 2));
        float mn0 = fmaxf(m0, mx0), mn1 = fmaxf(m1, mx1);
        float cr0 = exp2_fast(m0 - mn0), cr1 = exp2_fast(m1 - mn1);
        float s0 = 0.f, s1 = 0.f;
#pragma unroll
        for (int j = 0; j < 8; j++) {
            accS[j][0] = exp2_fast(accS[j][0] - mn0); s0 += accS[j][0];
            accS[j][1] = exp2_fast(accS[j][1] - mn0); s0 += accS[j][1];
            accS[j][2] = exp2_fast(accS[j][2] - mn1); s1 += accS[j][2];
            accS[j][3] = exp2_fast(accS[j][3] - mn1); s1 += accS[j][3];
        }
        s0 += __shfl_xor_sync(0xffffffffu, s0, 1);
        s0 += __shfl_xor_sync(0xffffffffu, s0, 2);
        s1 += __shfl_xor_sync(0xffffffffu, s1, 1);
        s1 += __shfl_xor_sync(0xffffffffu, s1, 2);
        l0 = l0 * cr0 + s0;
        l1 = l1 * cr1 + s1;
        m0 = mn0; m1 = mn1;
#pragma unroll
        for (int j = 0; j < 16; j++) {
            accO[j][0] *= cr0; accO[j][1] *= cr0;
            accO[j][2] *= cr1; accO[j][3] *= cr1;
        }

#pragma unroll
        for (int ks = 0; ks < 4; ks++) {
            int ja = 2 * ks, jb = 2 * ks + 1;
            uint32_t ph[4], pl[4];
            split2(accS[ja][0], accS[ja][1], ph[0], pl[0]);
            split2(accS[ja][2], accS[ja][3], ph[1], pl[1]);
            split2(accS[jb][0], accS[jb][1], ph[2], pl[2]);
            split2(accS[jb][2], accS[jb][3], ph[3], pl[3]);
#pragma unroll
            for (int j2 = 0; j2 < 16; j2++) {
                uint32_t vo = (uint32_t)((16 * ks + (lane & 15)) * FSTR + 8 * j2) * 2;
                uint32_t vf[2], vf2[2];
                ldsm_x2t(vf, Vh_s + vo);
                mma16816(accO[j2], ph, vf);
                mma16816(accO[j2], pl, vf);
                ldsm_x2t(vf2, Vl_s + vo);
                mma16816(accO[j2], ph, vf2);
            }
        }
    }

    float i0 = 1.f / l0, i1 = 1.f / l1;
#pragma unroll
    for (int j2 = 0; j2 < 16; j2++) {
        int col = 8 * j2 + 2 * (lane & 3);
        size_t o0 = hb + (size_t)r0g * DIM + col;
        size_t o1 = hb + (size_t)r1g * DIM + col;
        uint32_t h, l;
        split2(accO[j2][0] * i0, accO[j2][1] * i0, h, l);
        *(uint32_t*)(aoh + o0) = h; *(uint32_t*)(aol + o0) = l;
        split2(accO[j2][2] * i1, accO[j2][3] * i1, h, l);
        *(uint32_t*)(aoh + o1) = h; *(uint32_t*)(aol + o1) = l;
    }
}

// ---------------------------------------------------------------------------
extern "C" void kernel_launch(void* const* d_in, const int* in_sizes, int n_in,
                              void* d_out, int out_size) {
    const float* x  = (const float*)d_in[0];
    const float* wq = (const float*)d_in[1];
    const float* wk = (const float*)d_in[2];
    const float* wv = (const float*)d_in[3];
    const float* wo = (const float*)d_in[4];
    const float* fc = (const float*)d_in[5];
    const float* fs = (const float*)d_in[6];
    float* out = (float*)d_out;

    bf16 *xh, *xl, *wh, *wl, *qhp, *qlp, *khp, *klp, *vhp, *vlp, *aoh, *aol;
    cudaGetSymbolAddress((void**)&xh,  g_xh);
    cudaGetSymbolAddress((void**)&xl,  g_xl);
    cudaGetSymbolAddress((void**)&wh,  g_wh);
    cudaGetSymbolAddress((void**)&wl,  g_wl);
    cudaGetSymbolAddress((void**)&qhp, g_qh);
    cudaGetSymbolAddress((void**)&qlp, g_ql);
    cudaGetSymbolAddress((void**)&khp, g_kh);
    cudaGetSymbolAddress((void**)&klp, g_kl);
    cudaGetSymbolAddress((void**)&vhp, g_vh);
    cudaGetSymbolAddress((void**)&vlp, g_vl);
    cudaGetSymbolAddress((void**)&aoh, g_aoh);
    cudaGetSymbolAddress((void**)&aol, g_aol);

    cudaFuncSetAttribute(gemm_bf16<0>, cudaFuncAttributeMaxDynamicSharedMemorySize, GEMM_SMEM);
    cudaFuncSetAttribute(gemm_bf16<1>, cudaFuncAttributeMaxDynamicSharedMemorySize, GEMM_SMEM);
    cudaFuncSetAttribute(flash_mma,    cudaFuncAttributeMaxDynamicSharedMemorySize, FLASH_SMEM);

    // 1. split x (1 launch) and all 4 weights (1 launch) into bf16 hi/lo
    int nx2 = M_TOT * DIM / 2;
    int nw2 = DIM * DIM / 2;
    split_kernel<<<(nx2 + 255) / 256, 256>>>(x, xh, xl, nx2);
    dim3 wgrid((nw2 + 255) / 256, 4);
    split_w4<<<wgrid, 256>>>(wq, wk, wv, wo, wh, wl, nw2);

    // 2. fused QKV projections + RoPE + split (BN=64 tiles)
    dim3 ggrid(DIM / 64, M_TOT / 128, 3);   // (32, 32, 3)
    gemm_bf16<0><<<ggrid, 256, GEMM_SMEM>>>(xh, xl, wh, wl, nullptr,
                                            qhp, qlp, khp, klp, vhp, vlp, fc, fs);

    // 3. flash attention (bf16 3-pass, double-buffered K/V)
    dim3 fgrid(SEQ / 128, NH, BSZ);
    flash_mma<<<fgrid, 256, FLASH_SMEM>>>(qhp, qlp, khp, klp, vhp, vlp, aoh, aol);

    // 4. output projection (BN=64 tiles, fp32 out)
    dim3 ogrid(DIM / 64, M_TOT / 128, 1);   // (32, 32, 1)
    gemm_bf16<1><<<ogrid, 256, GEMM_SMEM>>>(aoh, aol, wh + (size_t)3 * DIM * DIM,
                                            wl + (size_t)3 * DIM * DIM, out,
                                            nullptr, nullptr, nullptr, nullptr,
                                            nullptr, nullptr, nullptr, nullptr);
}

// round 15
// speedup vs baseline: 1.2901x; 1.1431x over previous
#include <cuda_runtime.h>
#include <cuda_bf16.h>
#include <cstdint>
#include <math.h>

#define BSZ 2
#define SEQ 2048
#define DIM 2048
#define NH 16
#define HD 128
#define M_TOT (BSZ * SEQ)   // 4096

typedef __nv_bfloat16 bf16;

// ---------------- scratch (device globals; no allocs allowed) ----------------
__device__ bf16 g_xh[(size_t)M_TOT * DIM], g_xl[(size_t)M_TOT * DIM];
__device__ bf16 g_wh[(size_t)4 * DIM * DIM], g_wl[(size_t)4 * DIM * DIM];
__device__ bf16 g_qh[(size_t)M_TOT * DIM], g_ql[(size_t)M_TOT * DIM];
__device__ bf16 g_kh[(size_t)M_TOT * DIM], g_kl[(size_t)M_TOT * DIM];
__device__ bf16 g_vh[(size_t)M_TOT * DIM], g_vl[(size_t)M_TOT * DIM];
__device__ bf16 g_aoh[(size_t)M_TOT * DIM], g_aol[(size_t)M_TOT * DIM];

// ---------------- PTX helpers ----------------
__device__ __forceinline__ uint32_t smem_u32(const void* p) {
    uint32_t a;
    asm("{ .reg .u64 t; cvta.to.shared.u64 t, %1; cvt.u32.u64 %0, t; }" : "=r"(a) : "l"(p));
    return a;
}
__device__ __forceinline__ void ldsm_x4(uint32_t* r, uint32_t addr) {
    asm volatile("ldmatrix.sync.aligned.m8n8.x4.shared.b16 {%0,%1,%2,%3}, [%4];"
                 : "=r"(r[0]), "=r"(r[1]), "=r"(r[2]), "=r"(r[3]) : "r"(addr));
}
__device__ __forceinline__ void ldsm_x2(uint32_t* r, uint32_t addr) {
    asm volatile("ldmatrix.sync.aligned.m8n8.x2.shared.b16 {%0,%1}, [%2];"
                 : "=r"(r[0]), "=r"(r[1]) : "r"(addr));
}
__device__ __forceinline__ void ldsm_x2t(uint32_t* r, uint32_t addr) {
    asm volatile("ldmatrix.sync.aligned.m8n8.x2.trans.shared.b16 {%0,%1}, [%2];"
                 : "=r"(r[0]), "=r"(r[1]) : "r"(addr));
}
__device__ __forceinline__ void mma16816(float* d, const uint32_t* a, const uint32_t* b) {
    asm volatile(
        "mma.sync.aligned.m16n8k16.row.col.f32.bf16.bf16.f32 "
        "{%0,%1,%2,%3}, {%4,%5,%6,%7}, {%8,%9}, {%0,%1,%2,%3};"
        : "+f"(d[0]), "+f"(d[1]), "+f"(d[2]), "+f"(d[3])
        : "r"(a[0]), "r"(a[1]), "r"(a[2]), "r"(a[3]), "r"(b[0]), "r"(b[1]));
}
__device__ __forceinline__ void cp16(uint32_t dst, const void* src) {
    asm volatile("cp.async.cg.shared.global [%0], [%1], 16;" :: "r"(dst), "l"(src) : "memory");
}
#define CP_COMMIT() asm volatile("cp.async.commit_group;" ::: "memory")
#define CP_WAIT(n)  asm volatile("cp.async.wait_group %0;" :: "n"(n) : "memory")

// FFMA-only exp2 (x <= 0 path)
__device__ __forceinline__ float exp2_fast(float x) {
    x = fmaxf(x, -125.f);
    float r = x + 12582912.f;
    int  e = __float_as_int(r) - 0x4B400000;
    float f = x - (r - 12582912.f);
    float p = 1.5403530e-4f;
    p = fmaf(p, f, 1.3333558e-3f);
    p = fmaf(p, f, 9.6181291e-3f);
    p = fmaf(p, f, 5.5504109e-2f);
    p = fmaf(p, f, 2.4022651e-1f);
    p = fmaf(p, f, 6.9314718e-1f);
    p = fmaf(p, f, 1.0f);
    return __int_as_float(__float_as_int(p) + (e << 23));
}

// split floats -> packed bf16 hi + bf16 residual lo
__device__ __forceinline__ void split2(float a, float b, uint32_t& hi, uint32_t& lo) {
    bf16 ha = __float2bfloat16_rn(a), hb = __float2bfloat16_rn(b);
    float ra = a - __bfloat162float(ha), rb = b - __bfloat162float(hb);
    __nv_bfloat162 hp = __halves2bfloat162(ha, hb);
    __nv_bfloat162 lp = __floats2bfloat162_rn(ra, rb);
    hi = *(uint32_t*)&hp;
    lo = *(uint32_t*)&lp;
}

// ---------------- prep: fp32 -> bf16 hi/lo ----------------
__global__ void split_kernel(const float* __restrict__ src, bf16* __restrict__ hi,
                             bf16* __restrict__ lo, int n2) {
    int i = blockIdx.x * blockDim.x + threadIdx.x;
    if (i >= n2) return;
    float2 v = *(const float2*)(src + 2 * (size_t)i);
    uint32_t h, l;
    split2(v.x, v.y, h, l);
    *(uint32_t*)(hi + 2 * (size_t)i) = h;
    *(uint32_t*)(lo + 2 * (size_t)i) = l;
}
// 4 weight matrices in one launch (grid.y selects)
__global__ void split_w4(const float* __restrict__ w0, const float* __restrict__ w1,
                         const float* __restrict__ w2, const float* __restrict__ w3,
                         bf16* __restrict__ hi, bf16* __restrict__ lo, int n2) {
    int y = blockIdx.y;
    const float* src = (y == 0) ? w0 : (y == 1) ? w1 : (y == 2) ? w2 : w3;
    bf16* h = hi + (size_t)y * DIM * DIM;
    bf16* l = lo + (size_t)y * DIM * DIM;
    int i = blockIdx.x * blockDim.x + threadIdx.x;
    if (i >= n2) return;
    float2 v = *(const float2*)(src + 2 * (size_t)i);
    uint32_t hh, ll;
    split2(v.x, v.y, hh, ll);
    *(uint32_t*)(h + 2 * (size_t)i) = hh;
    *(uint32_t*)(l + 2 * (size_t)i) = ll;
}

// ===========================================================================
// bf16 GEMM, 3-pass split, BM=128 x BN=128 (R10-proven shape), KC=64,
// 3-stage cp.async, one sync per chunk.
// MODE 0: z in {0,1,2} = q,k,v; fused RoPE (q,k) + hi/lo split epilogue.
// MODE 1: fp32 epilogue to C.
// ===========================================================================
#define KC 64
#define ASTR 72
#define GTILE (128 * ASTR)
#define STAGE_ELEMS (4 * GTILE)
#define GEMM_SMEM (3 * STAGE_ELEMS * 2)   // 221184 bytes
#define SQ 0.127526015f                   // log2(e) / sqrt(128)

template <int MODE>
__global__ __launch_bounds__(256) void gemm_bf16(
    const bf16* __restrict__ Ah, const bf16* __restrict__ Al,
    const bf16* __restrict__ Bh_all, const bf16* __restrict__ Bl_all,
    float* __restrict__ C,
    bf16* __restrict__ qh, bf16* __restrict__ ql,
    bf16* __restrict__ kh, bf16* __restrict__ kl,
    bf16* __restrict__ vh, bf16* __restrict__ vl,
    const float* __restrict__ fc, const float* __restrict__ fs) {
    extern __shared__ bf16 sm[];
    int z = blockIdx.z;
    const bf16* Bh = Bh_all + (size_t)z * DIM * DIM;
    const bf16* Bl = Bl_all + (size_t)z * DIM * DIM;

    int t = threadIdx.x, lane = t & 31, warp = t >> 5;
    int wm = (warp & 1) * 64, wn = (warp >> 1) * 32;
    int bm = blockIdx.y * 128, bn = blockIdx.x * 128;
    const bf16* Agh = Ah + (size_t)bm * DIM;
    const bf16* Agl = Al + (size_t)bm * DIM;
    const bf16* Bgh = Bh + (size_t)bn * DIM;
    const bf16* Bgl = Bl + (size_t)bn * DIM;
    uint32_t sb = smem_u32(sm);

    float acc[4][4][4];
#pragma unroll
    for (int i = 0; i < 4; i++)
#pragma unroll
        for (int j = 0; j < 4; j++)
#pragma unroll
            for (int r = 0; r < 4; r++) acc[i][j][r] = 0.f;

    const int NCH = DIM / KC;   // 32

#define STAGE_LOAD(S, CC)                                                        \
    {                                                                            \
        int k0_ = (CC) * KC;                                                     \
        uint32_t ds = sb + (uint32_t)((S) * STAGE_ELEMS) * 2;                    \
        _Pragma("unroll")                                                        \
        for (int i_ = 0; i_ < 4; i_++) {                                         \
            int li = t + 256 * i_;                                               \
            int rr = li >> 3, seg = li & 7;                                      \
            uint32_t so = (uint32_t)(rr * ASTR + seg * 8) * 2;                   \
            size_t go = (size_t)rr * DIM + k0_ + seg * 8;                        \
            cp16(ds + so,                 Agh + go);                             \
            cp16(ds + GTILE * 2 + so,     Agl + go);                             \
            cp16(ds + 2 * GTILE * 2 + so, Bgh + go);                             \
            cp16(ds + 3 * GTILE * 2 + so, Bgl + go);                             \
        }                                                                        \
    }

    STAGE_LOAD(0, 0);
    CP_COMMIT();
    STAGE_LOAD(1, 1);
    CP_COMMIT();

    for (int c = 0; c < NCH; c++) {
        if (c + 2 < NCH) CP_WAIT(1); else CP_WAIT(0);
        __syncthreads();
        if (c + 2 < NCH) {
            STAGE_LOAD((c + 2) % 3, c + 2);
            CP_COMMIT();
        }

        int s = c % 3;
        uint32_t Ab  = sb + (uint32_t)(s * STAGE_ELEMS) * 2;
        uint32_t Alb = Ab + GTILE * 2;
        uint32_t Bb  = Ab + 2 * GTILE * 2;
        uint32_t Blb = Ab + 3 * GTILE * 2;

#pragma unroll
        for (int ks = 0; ks < 4; ks++) {
            uint32_t ah[4][4], al[4][4], bh[4][2], bl[4][2];
#pragma unroll
            for (int i = 0; i < 4; i++) {
                uint32_t ao = (uint32_t)((wm + i * 16 + (lane & 15)) * ASTR + ks * 16 + (lane >> 4) * 8) * 2;
                ldsm_x4(ah[i], Ab + ao);
                ldsm_x4(al[i], Alb + ao);
            }
#pragma unroll
            for (int j = 0; j < 4; j++) {
                uint32_t bo = (uint32_t)((wn + j * 8 + (lane & 7)) * ASTR + ks * 16 + ((lane >> 3) & 1) * 8) * 2;
                ldsm_x2(bh[j], Bb + bo);
                ldsm_x2(bl[j], Blb + bo);
            }
#pragma unroll
            for (int i = 0; i < 4; i++)
#pragma unroll
                for (int j = 0; j < 4; j++) mma16816(acc[i][j], ah[i], bh[j]);
#pragma unroll
            for (int i = 0; i < 4; i++)
#pragma unroll
                for (int j = 0; j < 4; j++) mma16816(acc[i][j], ah[i], bl[j]);
#pragma unroll
            for (int i = 0; i < 4; i++)
#pragma unroll
                for (int j = 0; j < 4; j++) mma16816(acc[i][j], al[i], bh[j]);
        }
    }

    if (MODE == 1) {
#pragma unroll
        for (int i = 0; i < 4; i++) {
            int r0 = bm + wm + i * 16 + (lane >> 2);
#pragma unroll
            for (int j = 0; j < 4; j++) {
                int c0 = bn + wn + j * 8 + (lane & 3) * 2;
                *(float2*)(C + (size_t)r0 * DIM + c0)       = make_float2(acc[i][j][0], acc[i][j][1]);
                *(float2*)(C + (size_t)(r0 + 8) * DIM + c0) = make_float2(acc[i][j][2], acc[i][j][3]);
            }
        }
    } else {
        // fused RoPE (z<2) + bf16 hi/lo split epilogue
        bf16* oh = (z == 0) ? qh : (z == 1) ? kh : vh;
        bf16* ol = (z == 0) ? ql : (z == 1) ? kl : vl;
#pragma unroll
        for (int i = 0; i < 4; i++) {
            int r0 = bm + wm + i * 16 + (lane >> 2);
            int r1 = r0 + 8;
#pragma unroll
            for (int j = 0; j < 4; j++) {
                int c0 = bn + wn + j * 8 + (lane & 3) * 2;
                float a0 = acc[i][j][0], b0 = acc[i][j][1];   // row r0, cols (c0, c0+1)
                float a1 = acc[i][j][2], b1 = acc[i][j][3];   // row r1
                if (z < 2) {
                    int ir = (c0 & (HD - 1)) >> 1;
                    int s0r = r0 & (SEQ - 1), s1r = r1 & (SEQ - 1);
                    float c_ = fc[s0r * (HD / 2) + ir], s_ = fs[s0r * (HD / 2) + ir];
                    float t0 = a0 * c_ - b0 * s_, t1 = a0 * s_ + b0 * c_;
                    c_ = fc[s1r * (HD / 2) + ir]; s_ = fs[s1r * (HD / 2) + ir];
                    float u0 = a1 * c_ - b1 * s_, u1 = a1 * s_ + b1 * c_;
                    if (z == 0) { t0 *= SQ; t1 *= SQ; u0 *= SQ; u1 *= SQ; }
                    a0 = t0; b0 = t1; a1 = u0; b1 = u1;
                }
                uint32_t h, l;
                split2(a0, b0, h, l);
                *(uint32_t*)(oh + (size_t)r0 * DIM + c0) = h;
                *(uint32_t*)(ol + (size_t)r0 * DIM + c0) = l;
                split2(a1, b1, h, l);
                *(uint32_t*)(oh + (size_t)r1 * DIM + c0) = h;
                *(uint32_t*)(ol + (size_t)r1 * DIM + c0) = l;
            }
        }
    }
}

// ===========================================================================
// Flash attention, mma.sync bf16 3-pass split, causal. BR=128, BC=64,
// double-buffered K/V, one sync per k-tile. Q fragments hoisted to registers
// (loaded once, reused across all k-tiles).
// ===========================================================================
#define FSTR 136
#define QT (128 * FSTR)
#define KT (64 * FSTR)
#define FSTAGE (4 * KT)
#define FLASH_SMEM ((2 * QT + 2 * FSTAGE) * 2)   // 208896 bytes

__global__ __launch_bounds__(256, 1) void flash_mma(
    const bf16* __restrict__ qh, const bf16* __restrict__ ql,
    const bf16* __restrict__ kh, const bf16* __restrict__ kl,
    const bf16* __restrict__ vh, const bf16* __restrict__ vl,
    bf16* __restrict__ aoh, bf16* __restrict__ aol) {
    extern __shared__ bf16 fsm[];
    int t = threadIdx.x, lane = t & 31, warp = t >> 5;
    int qblk = gridDim.x - 1 - blockIdx.x;
    int hh = blockIdx.y, b = blockIdx.z;
    int q0 = qblk * 128;
    size_t hb = (size_t)b * SEQ * DIM + (size_t)hh * HD;
    uint32_t sb = smem_u32(fsm);
    uint32_t Qh_s = sb, Ql_s = sb + QT * 2;
    uint32_t KV0  = sb + 2 * QT * 2;

#define FKV_LOAD(S, KT0)                                                         \
    {                                                                            \
        uint32_t ds = KV0 + (uint32_t)((S) * FSTAGE) * 2;                        \
        _Pragma("unroll")                                                        \
        for (int i_ = 0; i_ < 4; i_++) {                                         \
            int li = t + 256 * i_;                                               \
            int rr = li >> 4, seg = li & 15;                                     \
            size_t g = hb + (size_t)((KT0) + rr) * DIM + seg * 8;                \
            uint32_t so = (uint32_t)(rr * FSTR + seg * 8) * 2;                   \
            cp16(ds + so,              kh + g);                                  \
            cp16(ds + KT * 2 + so,     kl + g);                                  \
            cp16(ds + 2 * KT * 2 + so, vh + g);                                  \
            cp16(ds + 3 * KT * 2 + so, vl + g);                                  \
        }                                                                        \
    }

    // prologue: Q tiles + first K/V stage
#pragma unroll
    for (int i = 0; i < 8; i++) {
        int li = t + 256 * i;
        int r = li >> 4, seg = li & 15;
        size_t g = hb + (size_t)(q0 + r) * DIM + seg * 8;
        uint32_t so = (uint32_t)(r * FSTR + seg * 8) * 2;
        cp16(Qh_s + so, qh + g);
        cp16(Ql_s + so, ql + g);
    }
    CP_COMMIT();
    FKV_LOAD(0, 0);
    CP_COMMIT();

    // hoist Q fragments (hi+lo) into registers: invariant across k-tiles
    uint32_t qfh[8][4], qfl[8][4];
    CP_WAIT(1);          // Q group arrived
    __syncthreads();
#pragma unroll
    for (int ks = 0; ks < 8; ks++) {
        uint32_t ao = (uint32_t)((16 * warp + (lane & 15)) * FSTR + ks * 16 + (lane >> 4) * 8) * 2;
        ldsm_x4(qfh[ks], Qh_s + ao);
        ldsm_x4(qfl[ks], Ql_s + ao);
    }

    float accO[16][4];
#pragma unroll
    for (int j = 0; j < 16; j++)
#pragma unroll
        for (int r = 0; r < 4; r++) accO[j][r] = 0.f;
    float m0 = -1e30f, m1 = -1e30f, l0 = 0.f, l1 = 0.f;
    int rl0 = 16 * warp + (lane >> 2), rl1 = rl0 + 8;
    int r0g = q0 + rl0, r1g = q0 + rl1;

    int nk = 2 * qblk + 2;
    for (int kt = 0; kt < nk; kt++) {
        int k0 = kt * 64;
        CP_WAIT(0);
        __syncthreads();
        if (kt + 1 < nk) {
            FKV_LOAD((kt + 1) & 1, k0 + 64);
            CP_COMMIT();
        }
        uint32_t Kh_s = KV0 + (uint32_t)((kt & 1) * FSTAGE) * 2;
        uint32_t Kl_s = Kh_s + KT * 2;
        uint32_t Vh_s = Kh_s + 2 * KT * 2;
        uint32_t Vl_s = Kh_s + 3 * KT * 2;

        float accS[8][4];
#pragma unroll
        for (int j = 0; j < 8; j++)
#pragma unroll
            for (int r = 0; r < 4; r++) accS[j][r] = 0.f;

#pragma unroll
        for (int ks = 0; ks < 8; ks++) {
#pragma unroll
            for (int j = 0; j < 8; j++) {
                uint32_t bo = (uint32_t)((8 * j + (lane & 7)) * FSTR + ks * 16 + ((lane >> 3) & 1) * 8) * 2;
                uint32_t kf[2], kf2[2];
                ldsm_x2(kf, Kh_s + bo);
                mma16816(accS[j], qfh[ks], kf);
                mma16816(accS[j], qfl[ks], kf);
                ldsm_x2(kf2, Kl_s + bo);
                mma16816(accS[j], qfh[ks], kf2);
            }
        }

        if (kt >= 2 * qblk) {
            int cb = 2 * (lane & 3);
#pragma unroll
            for (int j = 0; j < 8; j++) {
                int c0 = k0 + 8 * j + cb;
                if (c0 > r0g)     accS[j][0] = -1e30f;
                if (c0 + 1 > r0g) accS[j][1] = -1e30f;
                if (c0 > r1g)     accS[j][2] = -1e30f;
                if (c0 + 1 > r1g) accS[j][3] = -1e30f;
            }
        }

        float mx0 = -1e30f, mx1 = -1e30f;
#pragma unroll
        for (int j = 0; j < 8; j++) {
            mx0 = fmaxf(mx0, fmaxf(accS[j][0], accS[j][1]));
            mx1 = fmaxf(mx1, fmaxf(accS[j][2], accS[j][3]));
        }
        mx0 = fmaxf(mx0, __shfl_xor_sync(0xffffffffu, mx0, 1));
        mx0 = fmaxf(mx0, __shfl_xor_sync(0xffffffffu, mx0, 2));
        mx1 = fmaxf(mx1, __shfl_xor_sync(0xffffffffu, mx1, 1));
        mx1 = fmaxf(mx1, __shfl_xor_sync(0xffffffffu, mx1, 2));
        float mn0 = fmaxf(m0, mx0), mn1 = fmaxf(m1, mx1);
        float cr0 = exp2_fast(m0 - mn0), cr1 = exp2_fast(m1 - mn1);
        float s0 = 0.f, s1 = 0.f;
#pragma unroll
        for (int j = 0; j < 8; j++) {
            accS[j][0] = exp2_fast(accS[j][0] - mn0); s0 += accS[j][0];
            accS[j][1] = exp2_fast(accS[j][1] - mn0); s0 += accS[j][1];
            accS[j][2] = exp2_fast(accS[j][2] - mn1); s1 += accS[j][2];
            accS[j][3] = exp2_fast(accS[j][3] - mn1); s1 += accS[j][3];
        }
        s0 += __shfl_xor_sync(0xffffffffu, s0, 1);
        s0 += __shfl_xor_sync(0xffffffffu, s0, 2);
        s1 += __shfl_xor_sync(0xffffffffu, s1, 1);
        s1 += __shfl_xor_sync(0xffffffffu, s1, 2);
        l0 = l0 * cr0 + s0;
        l1 = l1 * cr1 + s1;
        m0 = mn0; m1 = mn1;
#pragma unroll
        for (int j = 0; j < 16; j++) {
            accO[j][0] *= cr0; accO[j][1] *= cr0;
            accO[j][2] *= cr1; accO[j][3] *= cr1;
        }

#pragma unroll
        for (int ks = 0; ks < 4; ks++) {
            int ja = 2 * ks, jb = 2 * ks + 1;
            uint32_t ph[4], pl[4];
            split2(accS[ja][0], accS[ja][1], ph[0], pl[0]);
            split2(accS[ja][2], accS[ja][3], ph[1], pl[1]);
            split2(accS[jb][0], accS[jb][1], ph[2], pl[2]);
            split2(accS[jb][2], accS[jb][3], ph[3], pl[3]);
#pragma unroll
            for (int j2 = 0; j2 < 16; j2++) {
                uint32_t vo = (uint32_t)((16 * ks + (lane & 15)) * FSTR + 8 * j2) * 2;
                uint32_t vf[2], vf2[2];
                ldsm_x2t(vf, Vh_s + vo);
                mma16816(accO[j2], ph, vf);
                mma16816(accO[j2], pl, vf);
                ldsm_x2t(vf2, Vl_s + vo);
                mma16816(accO[j2], ph, vf2);
            }
        }
    }

    float i0 = 1.f / l0, i1 = 1.f / l1;
#pragma unroll
    for (int j2 = 0; j2 < 16; j2++) {
        int col = 8 * j2 + 2 * (lane & 3);
        size_t o0 = hb + (size_t)r0g * DIM + col;
        size_t o1 = hb + (size_t)r1g * DIM + col;
        uint32_t h, l;
        split2(accO[j2][0] * i0, accO[j2][1] * i0, h, l);
        *(uint32_t*)(aoh + o0) = h; *(uint32_t*)(aol + o0) = l;
        split2(accO[j2][2] * i1, accO[j2][3] * i1, h, l);
        *(uint32_t*)(aoh + o1) = h; *(uint32_t*)(aol + o1) = l;
    }
}

// ---------------------------------------------------------------------------
extern "C" void kernel_launch(void* const* d_in, const int* in_sizes, int n_in,
                              void* d_out, int out_size) {
    const float* x  = (const float*)d_in[0];
    const float* wq = (const float*)d_in[1];
    const float* wk = (const float*)d_in[2];
    const float* wv = (const float*)d_in[3];
    const float* wo = (const float*)d_in[4];
    const float* fc = (const float*)d_in[5];
    const float* fs = (const float*)d_in[6];
    float* out = (float*)d_out;

    bf16 *xh, *xl, *wh, *wl, *qhp, *qlp, *khp, *klp, *vhp, *vlp, *aoh, *aol;
    cudaGetSymbolAddress((void**)&xh,  g_xh);
    cudaGetSymbolAddress((void**)&xl,  g_xl);
    cudaGetSymbolAddress((void**)&wh,  g_wh);
    cudaGetSymbolAddress((void**)&wl,  g_wl);
    cudaGetSymbolAddress((void**)&qhp, g_qh);
    cudaGetSymbolAddress((void**)&qlp, g_ql);
    cudaGetSymbolAddress((void**)&khp, g_kh);
    cudaGetSymbolAddress((void**)&klp, g_kl);
    cudaGetSymbolAddress((void**)&vhp, g_vh);
    cudaGetSymbolAddress((void**)&vlp, g_vl);
    cudaGetSymbolAddress((void**)&aoh, g_aoh);
    cudaGetSymbolAddress((void**)&aol, g_aol);

    cudaFuncSetAttribute(gemm_bf16<0>, cudaFuncAttributeMaxDynamicSharedMemorySize, GEMM_SMEM);
    cudaFuncSetAttribute(gemm_bf16<1>, cudaFuncAttributeMaxDynamicSharedMemorySize, GEMM_SMEM);
    cudaFuncSetAttribute(flash_mma,    cudaFuncAttributeMaxDynamicSharedMemorySize, FLASH_SMEM);

    // 1. split x (1 launch) and all 4 weights (1 launch) into bf16 hi/lo
    int nx2 = M_TOT * DIM / 2;
    int nw2 = DIM * DIM / 2;
    split_kernel<<<(nx2 + 255) / 256, 256>>>(x, xh, xl, nx2);
    dim3 wgrid((nw2 + 255) / 256, 4);
    split_w4<<<wgrid, 256>>>(wq, wk, wv, wo, wh, wl, nw2);

    // 2. fused QKV projections + RoPE + split (BN=128 tiles, R10 shape)
    dim3 ggrid(DIM / 128, M_TOT / 128, 3);   // (16, 32, 3)
    gemm_bf16<0><<<ggrid, 256, GEMM_SMEM>>>(xh, xl, wh, wl, nullptr,
                                            qhp, qlp, khp, klp, vhp, vlp, fc, fs);

    // 3. flash attention (bf16 3-pass, double-buffered K/V, Q in registers)
    dim3 fgrid(SEQ / 128, NH, BSZ);
    flash_mma<<<fgrid, 256, FLASH_SMEM>>>(qhp, qlp, khp, klp, vhp, vlp, aoh, aol);

    // 4. output projection (BN=128, fp32 out)
    dim3 ogrid(DIM / 128, M_TOT / 128, 1);   // (16, 32, 1)
    gemm_bf16<1><<<ogrid, 256, GEMM_SMEM>>>(aoh, aol, wh + (size_t)3 * DIM * DIM,
                                            wl + (size_t)3 * DIM * DIM, out,
                                            nullptr, nullptr, nullptr, nullptr,
                                            nullptr, nullptr, nullptr, nullptr);
}